// round 15
// baseline (speedup 1.0000x reference)
#include <cuda_runtime.h>
#include <cstdint>

// out = x * (1 - mask), mask broadcasts over C=3.
// x:    [B=64, C=3, H=512, W=512] f32
// mask: [B=64, 1,   H=512, W=512] f32, exactly 0/1 in large rectangles.
//
// R5 trick: mask==1 -> out is exactly 0.0f -> skip x loads.
// R11: 256-bit accesses (ld/st.global.v8.f32), warp = 1024B contiguous.
// R14: TWO v8 chunks per thread, interleaved by 2*THREADS float4s so both
// chunks stay warp-coalesced. Up to 8 v8 loads in flight per thread
// (256B MLP) to cover DRAM latency at low occupancy. No min-blocks clause
// (regs ~80, must not spill).

static constexpr int Cc = 3;
static constexpr int HW = 512 * 512;
static constexpr int HW4 = HW / 4;        // 65536 float4 per plane
static constexpr int THREADS = 256;
// Each CTA covers THREADS*4 float4 positions (2 v8 chunks of 2 float4 each).
static constexpr int F4_PER_CTA = THREADS * 4;

__device__ __forceinline__ void ldg256(const float4* p, float4& a, float4& b) {
    asm volatile("ld.global.v8.f32 {%0,%1,%2,%3,%4,%5,%6,%7}, [%8];"
                 : "=f"(a.x), "=f"(a.y), "=f"(a.z), "=f"(a.w),
                   "=f"(b.x), "=f"(b.y), "=f"(b.z), "=f"(b.w)
                 : "l"(p));
}

__device__ __forceinline__ void stg256(float4* p, float4 a, float4 b) {
    asm volatile("st.global.v8.f32 [%0], {%1,%2,%3,%4,%5,%6,%7,%8};"
                 :: "l"(p),
                    "f"(a.x), "f"(a.y), "f"(a.z), "f"(a.w),
                    "f"(b.x), "f"(b.y), "f"(b.z), "f"(b.w)
                 : "memory");
}

__device__ __forceinline__ float4 blend(float4 xv, float4 m) {
    return make_float4(xv.x * (1.0f - m.x), xv.y * (1.0f - m.y),
                       xv.z * (1.0f - m.z), xv.w * (1.0f - m.w));
}

__device__ __forceinline__ bool allone(float4 m) {
    return (m.x == 1.0f) & (m.y == 1.0f) & (m.z == 1.0f) & (m.w == 1.0f);
}

__global__ __launch_bounds__(THREADS)
void random_mask_kernel(const float4* __restrict__ x,
                        const float4* __restrict__ mask,
                        float4* __restrict__ out) {
    const int b = blockIdx.y;                                       // batch
    // Chunk 0 at float4-index u0, chunk 1 at u0 + 2*THREADS.
    const int u0 = blockIdx.x * F4_PER_CTA + threadIdx.x * 2;
    const int u1 = u0 + 2 * THREADS;

    const long long mbase = (long long)b * HW4;
    const long long xbase = (long long)(b * Cc) * HW4;

    // Both mask v8 loads first (MLP 2 immediately).
    float4 mA0, mA1, mB0, mB1;
    ldg256(&mask[mbase + u0], mA0, mA1);
    ldg256(&mask[mbase + u1], mB0, mB1);

    const bool fmA = allone(mA0) & allone(mA1);
    const bool fmB = allone(mB0) & allone(mB1);

    const long long pA = xbase + u0;
    const long long pB = xbase + u1;
    const float4 z = make_float4(0.0f, 0.0f, 0.0f, 0.0f);

    if (fmA & fmB) {
        stg256(&out[pA], z, z); stg256(&out[pA + HW4], z, z); stg256(&out[pA + 2 * HW4], z, z);
        stg256(&out[pB], z, z); stg256(&out[pB + HW4], z, z); stg256(&out[pB + 2 * HW4], z, z);
        return;
    }

    if (!fmA & !fmB) {
        // Both live: 6 v8 loads in flight.
        float4 aA0, aA1, bA0, bA1, cA0, cA1;
        float4 aB0, aB1, bB0, bB1, cB0, cB1;
        ldg256(&x[pA],           aA0, aA1);
        ldg256(&x[pB],           aB0, aB1);
        ldg256(&x[pA + HW4],     bA0, bA1);
        ldg256(&x[pB + HW4],     bB0, bB1);
        ldg256(&x[pA + 2 * HW4], cA0, cA1);
        ldg256(&x[pB + 2 * HW4], cB0, cB1);

        stg256(&out[pA],           blend(aA0, mA0), blend(aA1, mA1));
        stg256(&out[pB],           blend(aB0, mB0), blend(aB1, mB1));
        stg256(&out[pA + HW4],     blend(bA0, mA0), blend(bA1, mA1));
        stg256(&out[pB + HW4],     blend(bB0, mB0), blend(bB1, mB1));
        stg256(&out[pA + 2 * HW4], blend(cA0, mA0), blend(cA1, mA1));
        stg256(&out[pB + 2 * HW4], blend(cB0, mB0), blend(cB1, mB1));
        return;
    }

    // Mixed: exactly one chunk live.
    const long long pl = fmA ? pB : pA;
    const long long pm = fmA ? pA : pB;
    const float4 ml0 = fmA ? mB0 : mA0;
    const float4 ml1 = fmA ? mB1 : mA1;

    float4 a0, a1, b0, b1, c0, c1;
    ldg256(&x[pl],           a0, a1);
    ldg256(&x[pl + HW4],     b0, b1);
    ldg256(&x[pl + 2 * HW4], c0, c1);

    stg256(&out[pm], z, z); stg256(&out[pm + HW4], z, z); stg256(&out[pm + 2 * HW4], z, z);
    stg256(&out[pl],           blend(a0, ml0), blend(a1, ml1));
    stg256(&out[pl + HW4],     blend(b0, ml0), blend(b1, ml1));
    stg256(&out[pl + 2 * HW4], blend(c0, ml0), blend(c1, ml1));
}

extern "C" void kernel_launch(void* const* d_in, const int* in_sizes, int n_in,
                              void* d_out, int out_size) {
    const float4* x    = (const float4*)d_in[0];
    const float4* mask = (const float4*)d_in[1];
    float4* out        = (float4*)d_out;

    const int B = in_sizes[1] / HW;                   // 64
    dim3 grid(HW4 / F4_PER_CTA, B);                   // (64, 64)
    random_mask_kernel<<<grid, THREADS>>>(x, mask, out);
}